// round 3
// baseline (speedup 1.0000x reference)
#include <cuda_runtime.h>
#include <cstdint>

// ---------------------------------------------------------------------------
// IoU loss (2D + scatter-rebuilt 3D) without materializing the 3D volume.
//   inter2 = sum over DISTINCT voxels (dedup via 2MB bitmap atomicOr) of
//            winner * m3[voxel];  union2 = sum(winner) + sum(m3) - inter2.
// Bottleneck is L1tex wavefront issue (3 random ops / sample). This version:
//   - block-role split: gather blocks (samples) || stream blocks (m3 sum, 2D)
//   - finalize folded into fused kernel (last-block-done)
//   - 8-sample batches for MLP
// ---------------------------------------------------------------------------

#define DMAX   256
#define BITN   ((DMAX * DMAX * DMAX) / 32)   // 512K words = 2MB

__device__ unsigned g_bitmap[BITN];
__device__ double   g_acc[5];
// [0]=S(o2*m2) [1]=S(o2+m2) [2]=S(win*m3) [3]=S(win) [4]=S(m3)
__device__ unsigned g_done;

// ---------------------------------------------------------------------------
__global__ void zero_kernel() {
    const int tid    = blockIdx.x * blockDim.x + threadIdx.x;
    const int stride = gridDim.x * blockDim.x;
    uint4* b4 = reinterpret_cast<uint4*>(g_bitmap);
    const uint4 z = make_uint4(0u, 0u, 0u, 0u);
    for (int i = tid; i < BITN / 4; i += stride) b4[i] = z;
    if (tid < 5) g_acc[tid] = 0.0;
    if (tid == 5) g_done = 0u;
}

// ---------------------------------------------------------------------------
__device__ __forceinline__ void block_reduce_pair(float a, float b,
                                                  double* accA, double* accB) {
    #pragma unroll
    for (int o = 16; o > 0; o >>= 1) {
        a += __shfl_xor_sync(0xFFFFFFFFu, a, o);
        b += __shfl_xor_sync(0xFFFFFFFFu, b, o);
    }
    __shared__ float sa[32], sb[32];
    const int lane = threadIdx.x & 31;
    const int wrp  = threadIdx.x >> 5;
    __syncthreads();
    if (lane == 0) { sa[wrp] = a; sb[wrp] = b; }
    __syncthreads();
    if (wrp == 0) {
        const int nw = (blockDim.x + 31) >> 5;
        a = (lane < nw) ? sa[lane] : 0.f;
        b = (lane < nw) ? sb[lane] : 0.f;
        #pragma unroll
        for (int o = 16; o > 0; o >>= 1) {
            a += __shfl_xor_sync(0xFFFFFFFFu, a, o);
            b += __shfl_xor_sync(0xFFFFFFFFu, b, o);
        }
        if (lane == 0) {
            atomicAdd(accA, (double)a);
            atomicAdd(accB, (double)b);
        }
    }
}

// ---------------------------------------------------------------------------
__device__ __forceinline__ void process_sample(const float* __restrict__ o2d,
                                               const float* __restrict__ m3d,
                                               int id, int x, int y, int z, int D,
                                               float& inter2, float& sumv) {
    const unsigned vox = ((unsigned)x * (unsigned)D + (unsigned)y) * (unsigned)D
                       + (unsigned)z;
    const float v = __ldg(o2d + id);
    const float m = __ldg(m3d + vox);
    const unsigned bit = 1u << (vox & 31u);
    const unsigned old = atomicOr(&g_bitmap[vox >> 5], bit);
    if (!(old & bit)) { inter2 += v * m; sumv += v; }
}

// ---------------------------------------------------------------------------
__global__ void __launch_bounds__(256)
fused_kernel(const float* __restrict__ o2d,
             const float* __restrict__ m2d,
             const float* __restrict__ m3d,
             const int*   __restrict__ index,
             const int*   __restrict__ midxyz,
             int N, int M, int V, int D, int GB,
             float* __restrict__ out) {
    const int bx = blockIdx.x;

    if (bx < GB) {
        // ================= gather role: scattered samples =================
        const int tid    = bx * blockDim.x + threadIdx.x;
        const int stride = GB * blockDim.x;
        float inter2 = 0.f, sumv = 0.f;

        const int n8 = N >> 3;
        const int4* idx4 = reinterpret_cast<const int4*>(index);
        const int4* mid4 = reinterpret_cast<const int4*>(midxyz);
        for (int i = tid; i < n8; i += stride) {
            const int4 ia = idx4[2 * i + 0];
            const int4 ib = idx4[2 * i + 1];
            const int4 m0 = mid4[6 * i + 0];
            const int4 m1 = mid4[6 * i + 1];
            const int4 m2 = mid4[6 * i + 2];
            const int4 m3 = mid4[6 * i + 3];
            const int4 m4 = mid4[6 * i + 4];
            const int4 m5 = mid4[6 * i + 5];
            process_sample(o2d, m3d, ia.x, m0.x, m0.y, m0.z, D, inter2, sumv);
            process_sample(o2d, m3d, ia.y, m0.w, m1.x, m1.y, D, inter2, sumv);
            process_sample(o2d, m3d, ia.z, m1.z, m1.w, m2.x, D, inter2, sumv);
            process_sample(o2d, m3d, ia.w, m2.y, m2.z, m2.w, D, inter2, sumv);
            process_sample(o2d, m3d, ib.x, m3.x, m3.y, m3.z, D, inter2, sumv);
            process_sample(o2d, m3d, ib.y, m3.w, m4.x, m4.y, D, inter2, sumv);
            process_sample(o2d, m3d, ib.z, m4.z, m4.w, m5.x, D, inter2, sumv);
            process_sample(o2d, m3d, ib.w, m5.y, m5.z, m5.w, D, inter2, sumv);
        }
        for (int i = (n8 << 3) + tid; i < N; i += stride) {
            process_sample(o2d, m3d, index[i],
                           midxyz[3 * i], midxyz[3 * i + 1], midxyz[3 * i + 2],
                           D, inter2, sumv);
        }
        block_reduce_pair(inter2, sumv, &g_acc[2], &g_acc[3]);
    } else {
        // ================= stream role: m3 sum + 2D IoU =================
        const int tid    = (bx - GB) * blockDim.x + threadIdx.x;
        const int stride = (gridDim.x - GB) * blockDim.x;

        float sm3 = 0.f;
        {
            const int v4 = V >> 2;
            const float4* m4 = reinterpret_cast<const float4*>(m3d);
            for (int i = tid; i < v4; i += stride) {
                const float4 m = m4[i];
                sm3 += (m.x + m.y) + (m.z + m.w);
            }
            for (int i = (v4 << 2) + tid; i < V; i += stride) sm3 += m3d[i];
        }

        float a2 = 0.f, b2 = 0.f;
        {
            const int m4n = M >> 2;
            const float4* o4 = reinterpret_cast<const float4*>(o2d);
            const float4* q4 = reinterpret_cast<const float4*>(m2d);
            for (int i = tid; i < m4n; i += stride) {
                const float4 o = o4[i];
                const float4 m = q4[i];
                a2 += o.x * m.x + o.y * m.y + o.z * m.z + o.w * m.w;
                b2 += (o.x + m.x) + (o.y + m.y) + (o.z + m.z) + (o.w + m.w);
            }
            for (int i = (m4n << 2) + tid; i < M; i += stride) {
                const float o = o2d[i], m = m2d[i];
                a2 += o * m;
                b2 += o + m;
            }
        }
        block_reduce_pair(a2, b2, &g_acc[0], &g_acc[1]);
        block_reduce_pair(sm3, 0.f, &g_acc[4], &g_acc[4]);
    }

    // ================= fused finalize: last block computes the loss ========
    __syncthreads();
    if (threadIdx.x == 0) {
        __threadfence();
        const unsigned t = atomicAdd(&g_done, 1u);
        if (t == gridDim.x - 1u) {
            const double eps = 1e-8;
            const double A1 = g_acc[0], B1 = g_acc[1];
            const double I2 = g_acc[2], SV = g_acc[3], SM = g_acc[4];
            const double l1 = 1.0 - (A1 + eps) / ((B1 - A1) + eps);
            const double l2 = 1.0 - (I2 + eps) / ((SV + SM - I2) + eps);
            out[0] = (float)l1;
            out[1] = (float)l2;
            out[2] = (float)(l1 + l2);
        }
    }
}

// ---------------------------------------------------------------------------
extern "C" void kernel_launch(void* const* d_in, const int* in_sizes, int n_in,
                              void* d_out, int out_size) {
    const float* o2d    = (const float*)d_in[0];
    const float* m2d    = (const float*)d_in[1];
    const float* m3d    = (const float*)d_in[2];
    const int*   index  = (const int*)  d_in[3];
    const int*   midxyz = (const int*)  d_in[4];

    const int M = in_sizes[0];        // H2*W2
    const int V = in_sizes[2];        // D^3
    const int N = in_sizes[3];        // samples

    int D = 1;
    while ((long long)(D + 1) * (D + 1) * (D + 1) <= (long long)V) ++D;
    if (D > DMAX) D = DMAX;

    float* out = (float*)d_out;

    const int TPB  = 256;
    const int GRID = 148 * 16;        // 2368 blocks
    const int GB   = 1600;            // gather blocks (~68% of issue cost)

    zero_kernel<<<148 * 4, TPB>>>();
    fused_kernel<<<GRID, TPB>>>(o2d, m2d, m3d, index, midxyz,
                                N, M, V, D, GB, out);
}

// round 4
// speedup vs baseline: 1.2645x; 1.2645x over previous
#include <cuda_runtime.h>
#include <cstdint>

// ---------------------------------------------------------------------------
// IoU loss (2D + scatter-rebuilt 3D) without materializing the 3D volume.
//   inter2 = sum over DISTINCT voxels (dedup via 2MB bitmap atomicOr) of
//            winner * m3[voxel];  union2 = sum(winner) + sum(m3) - inter2.
// Latency-bound on random gathers. This version maximizes gather L2-hit rate:
//   - phases ordered: m3 sum -> 2D loop -> gathers (sequential passes warm L2
//     with m3d + o2d, which the gather phase then hits)
//   - one-shot streams (index, midxyz, m2d) loaded evict-first (__ldcs)
//   - uniform per-thread phases (no role split), finalize folded in
// ---------------------------------------------------------------------------

#define DMAX   256
#define BITN   ((DMAX * DMAX * DMAX) / 32)   // 512K words = 2MB

__device__ unsigned g_bitmap[BITN];
__device__ double   g_acc[5];
// [0]=S(o2*m2) [1]=S(o2+m2) [2]=S(win*m3) [3]=S(win) [4]=S(m3)
__device__ unsigned g_done;

// ---------------------------------------------------------------------------
__global__ void zero_kernel() {
    const int tid    = blockIdx.x * blockDim.x + threadIdx.x;
    const int stride = gridDim.x * blockDim.x;
    uint4* b4 = reinterpret_cast<uint4*>(g_bitmap);
    const uint4 z = make_uint4(0u, 0u, 0u, 0u);
    for (int i = tid; i < BITN / 4; i += stride) b4[i] = z;
    if (tid < 5) g_acc[tid] = 0.0;
    if (tid == 5) g_done = 0u;
}

// ---------------------------------------------------------------------------
__device__ __forceinline__ void block_reduce_pair(float a, float b,
                                                  double* accA, double* accB) {
    #pragma unroll
    for (int o = 16; o > 0; o >>= 1) {
        a += __shfl_xor_sync(0xFFFFFFFFu, a, o);
        b += __shfl_xor_sync(0xFFFFFFFFu, b, o);
    }
    __shared__ float sa[32], sb[32];
    const int lane = threadIdx.x & 31;
    const int wrp  = threadIdx.x >> 5;
    __syncthreads();
    if (lane == 0) { sa[wrp] = a; sb[wrp] = b; }
    __syncthreads();
    if (wrp == 0) {
        const int nw = (blockDim.x + 31) >> 5;
        a = (lane < nw) ? sa[lane] : 0.f;
        b = (lane < nw) ? sb[lane] : 0.f;
        #pragma unroll
        for (int o = 16; o > 0; o >>= 1) {
            a += __shfl_xor_sync(0xFFFFFFFFu, a, o);
            b += __shfl_xor_sync(0xFFFFFFFFu, b, o);
        }
        if (lane == 0) {
            atomicAdd(accA, (double)a);
            atomicAdd(accB, (double)b);
        }
    }
}

// ---------------------------------------------------------------------------
__device__ __forceinline__ void process_sample(const float* __restrict__ o2d,
                                               const float* __restrict__ m3d,
                                               int id, int x, int y, int z, int D,
                                               float& inter2, float& sumv) {
    const unsigned vox = ((unsigned)x * (unsigned)D + (unsigned)y) * (unsigned)D
                       + (unsigned)z;
    const float v = __ldg(o2d + id);
    const float m = __ldg(m3d + vox);
    const unsigned bit = 1u << (vox & 31u);
    const unsigned old = atomicOr(&g_bitmap[vox >> 5], bit);
    if (!(old & bit)) { inter2 += v * m; sumv += v; }
}

__device__ __forceinline__ int4 ldcs_int4(const int4* p) {
    int4 r;
    asm volatile("ld.global.cs.v4.b32 {%0,%1,%2,%3}, [%4];"
                 : "=r"(r.x), "=r"(r.y), "=r"(r.z), "=r"(r.w) : "l"(p));
    return r;
}
__device__ __forceinline__ float4 ldcs_float4(const float4* p) {
    float4 r;
    asm volatile("ld.global.cs.v4.f32 {%0,%1,%2,%3}, [%4];"
                 : "=f"(r.x), "=f"(r.y), "=f"(r.z), "=f"(r.w) : "l"(p));
    return r;
}

// ---------------------------------------------------------------------------
__global__ void __launch_bounds__(256)
fused_kernel(const float* __restrict__ o2d,
             const float* __restrict__ m2d,
             const float* __restrict__ m3d,
             const int*   __restrict__ index,
             const int*   __restrict__ midxyz,
             int N, int M, int V, int D,
             float* __restrict__ out) {
    const int tid    = blockIdx.x * blockDim.x + threadIdx.x;
    const int stride = gridDim.x * blockDim.x;

    // ---- phase 1: sequential sum of mask_3D (warms L2 with m3d) ----
    float sm3 = 0.f;
    {
        const int v4 = V >> 2;
        const float4* m4 = reinterpret_cast<const float4*>(m3d);
        for (int i = tid; i < v4; i += stride) {
            const float4 m = m4[i];          // keep in L2 (reused by gathers)
            sm3 += (m.x + m.y) + (m.z + m.w);
        }
        for (int i = (v4 << 2) + tid; i < V; i += stride) sm3 += m3d[i];
    }

    // ---- phase 2: 2D IoU partial sums (warms L2 with o2d) ----
    float a2 = 0.f, b2 = 0.f;
    {
        const int m4n = M >> 2;
        const float4* o4 = reinterpret_cast<const float4*>(o2d);
        const float4* q4 = reinterpret_cast<const float4*>(m2d);
        for (int i = tid; i < m4n; i += stride) {
            const float4 o = o4[i];          // keep in L2 (reused by gathers)
            const float4 m = ldcs_float4(q4 + i);  // one-shot: evict-first
            a2 += o.x * m.x + o.y * m.y + o.z * m.z + o.w * m.w;
            b2 += (o.x + m.x) + (o.y + m.y) + (o.z + m.z) + (o.w + m.w);
        }
        for (int i = (m4n << 2) + tid; i < M; i += stride) {
            const float o = o2d[i], m = m2d[i];
            a2 += o * m;
            b2 += o + m;
        }
    }

    // ---- phase 3: scattered samples (gathers should now hit L2) ----
    float inter2 = 0.f, sumv = 0.f;
    {
        const int n8 = N >> 3;
        const int4* idx4 = reinterpret_cast<const int4*>(index);
        const int4* mid4 = reinterpret_cast<const int4*>(midxyz);
        for (int i = tid; i < n8; i += stride) {
            const int4 ia = ldcs_int4(idx4 + 2 * i + 0);
            const int4 ib = ldcs_int4(idx4 + 2 * i + 1);
            const int4 m0 = ldcs_int4(mid4 + 6 * i + 0);
            const int4 m1 = ldcs_int4(mid4 + 6 * i + 1);
            const int4 m2 = ldcs_int4(mid4 + 6 * i + 2);
            const int4 m3 = ldcs_int4(mid4 + 6 * i + 3);
            const int4 m4 = ldcs_int4(mid4 + 6 * i + 4);
            const int4 m5 = ldcs_int4(mid4 + 6 * i + 5);
            process_sample(o2d, m3d, ia.x, m0.x, m0.y, m0.z, D, inter2, sumv);
            process_sample(o2d, m3d, ia.y, m0.w, m1.x, m1.y, D, inter2, sumv);
            process_sample(o2d, m3d, ia.z, m1.z, m1.w, m2.x, D, inter2, sumv);
            process_sample(o2d, m3d, ia.w, m2.y, m2.z, m2.w, D, inter2, sumv);
            process_sample(o2d, m3d, ib.x, m3.x, m3.y, m3.z, D, inter2, sumv);
            process_sample(o2d, m3d, ib.y, m3.w, m4.x, m4.y, D, inter2, sumv);
            process_sample(o2d, m3d, ib.z, m4.z, m4.w, m5.x, D, inter2, sumv);
            process_sample(o2d, m3d, ib.w, m5.y, m5.z, m5.w, D, inter2, sumv);
        }
        for (int i = (n8 << 3) + tid; i < N; i += stride) {
            process_sample(o2d, m3d, index[i],
                           midxyz[3 * i], midxyz[3 * i + 1], midxyz[3 * i + 2],
                           D, inter2, sumv);
        }
    }

    block_reduce_pair(a2, b2, &g_acc[0], &g_acc[1]);
    block_reduce_pair(inter2, sumv, &g_acc[2], &g_acc[3]);
    block_reduce_pair(sm3, 0.f, &g_acc[4], &g_acc[4]);

    // ---- fused finalize: last block computes the loss ----
    __syncthreads();
    if (threadIdx.x == 0) {
        __threadfence();
        const unsigned t = atomicAdd(&g_done, 1u);
        if (t == gridDim.x - 1u) {
            const double eps = 1e-8;
            const double A1 = g_acc[0], B1 = g_acc[1];
            const double I2 = g_acc[2], SV = g_acc[3], SM = g_acc[4];
            const double l1 = 1.0 - (A1 + eps) / ((B1 - A1) + eps);
            const double l2 = 1.0 - (I2 + eps) / ((SV + SM - I2) + eps);
            out[0] = (float)l1;
            out[1] = (float)l2;
            out[2] = (float)(l1 + l2);
        }
    }
}

// ---------------------------------------------------------------------------
extern "C" void kernel_launch(void* const* d_in, const int* in_sizes, int n_in,
                              void* d_out, int out_size) {
    const float* o2d    = (const float*)d_in[0];
    const float* m2d    = (const float*)d_in[1];
    const float* m3d    = (const float*)d_in[2];
    const int*   index  = (const int*)  d_in[3];
    const int*   midxyz = (const int*)  d_in[4];

    const int M = in_sizes[0];        // H2*W2
    const int V = in_sizes[2];        // D^3
    const int N = in_sizes[3];        // samples

    int D = 1;
    while ((long long)(D + 1) * (D + 1) * (D + 1) <= (long long)V) ++D;
    if (D > DMAX) D = DMAX;

    float* out = (float*)d_out;

    const int TPB  = 256;
    const int GRID = 148 * 16;        // 2368 blocks

    zero_kernel<<<148 * 4, TPB>>>();
    fused_kernel<<<GRID, TPB>>>(o2d, m2d, m3d, index, midxyz, N, M, V, D, out);
}

// round 5
// speedup vs baseline: 1.4491x; 1.1460x over previous
#include <cuda_runtime.h>
#include <cstdint>

// ---------------------------------------------------------------------------
// IoU loss (2D + scatter-rebuilt 3D) without materializing the 3D volume.
//   inter2 = sum over DISTINCT voxels (dedup via 2MB bitmap atomicOr) of
//            winner * m3[voxel];  union2 = sum(winner) + sum(m3) - inter2.
// Software-interleaved: every loop iteration issues BOTH coalesced stream
// loads (DRAM-bound work) and a 4-sample scattered batch (L1tex-wavefront
// bound work), so the two bottlenecks overlap instead of running serially.
// ---------------------------------------------------------------------------

#define DMAX   256
#define BITN   ((DMAX * DMAX * DMAX) / 32)   // 512K words = 2MB

__device__ unsigned g_bitmap[BITN];
__device__ double   g_acc[5];
// [0]=S(o2*m2) [1]=S(o2+m2) [2]=S(win*m3) [3]=S(win) [4]=S(m3)
__device__ unsigned g_done;

// ---------------------------------------------------------------------------
__global__ void zero_kernel() {
    const int tid    = blockIdx.x * blockDim.x + threadIdx.x;
    const int stride = gridDim.x * blockDim.x;
    uint4* b4 = reinterpret_cast<uint4*>(g_bitmap);
    const uint4 z = make_uint4(0u, 0u, 0u, 0u);
    for (int i = tid; i < BITN / 4; i += stride) b4[i] = z;
    if (tid < 5) g_acc[tid] = 0.0;
    if (tid == 5) g_done = 0u;
}

// ---------------------------------------------------------------------------
__device__ __forceinline__ void block_reduce_pair(float a, float b,
                                                  double* accA, double* accB) {
    #pragma unroll
    for (int o = 16; o > 0; o >>= 1) {
        a += __shfl_xor_sync(0xFFFFFFFFu, a, o);
        b += __shfl_xor_sync(0xFFFFFFFFu, b, o);
    }
    __shared__ float sa[32], sb[32];
    const int lane = threadIdx.x & 31;
    const int wrp  = threadIdx.x >> 5;
    __syncthreads();
    if (lane == 0) { sa[wrp] = a; sb[wrp] = b; }
    __syncthreads();
    if (wrp == 0) {
        const int nw = (blockDim.x + 31) >> 5;
        a = (lane < nw) ? sa[lane] : 0.f;
        b = (lane < nw) ? sb[lane] : 0.f;
        #pragma unroll
        for (int o = 16; o > 0; o >>= 1) {
            a += __shfl_xor_sync(0xFFFFFFFFu, a, o);
            b += __shfl_xor_sync(0xFFFFFFFFu, b, o);
        }
        if (lane == 0) {
            atomicAdd(accA, (double)a);
            atomicAdd(accB, (double)b);
        }
    }
}

// ---------------------------------------------------------------------------
__device__ __forceinline__ void process_sample(const float* __restrict__ o2d,
                                               const float* __restrict__ m3d,
                                               int id, int x, int y, int z, int D,
                                               float& inter2, float& sumv) {
    const unsigned vox = ((unsigned)x * (unsigned)D + (unsigned)y) * (unsigned)D
                       + (unsigned)z;
    const float v = __ldg(o2d + id);
    const float m = __ldg(m3d + vox);
    const unsigned bit = 1u << (vox & 31u);
    const unsigned old = atomicOr(&g_bitmap[vox >> 5], bit);
    if (!(old & bit)) { inter2 += v * m; sumv += v; }
}

__device__ __forceinline__ int4 ldcs_int4(const int4* p) {
    int4 r;
    asm volatile("ld.global.cs.v4.b32 {%0,%1,%2,%3}, [%4];"
                 : "=r"(r.x), "=r"(r.y), "=r"(r.z), "=r"(r.w) : "l"(p));
    return r;
}
__device__ __forceinline__ float4 ldcs_float4(const float4* p) {
    float4 r;
    asm volatile("ld.global.cs.v4.f32 {%0,%1,%2,%3}, [%4];"
                 : "=f"(r.x), "=f"(r.y), "=f"(r.z), "=f"(r.w) : "l"(p));
    return r;
}

// ---------------------------------------------------------------------------
__global__ void __launch_bounds__(256)
fused_kernel(const float* __restrict__ o2d,
             const float* __restrict__ m2d,
             const float* __restrict__ m3d,
             const int*   __restrict__ index,
             const int*   __restrict__ midxyz,
             int N, int M, int V, int D,
             float* __restrict__ out) {
    const int tid    = blockIdx.x * blockDim.x + threadIdx.x;
    const int stride = gridDim.x * blockDim.x;

    float inter2 = 0.f, sumv = 0.f;   // 3D scattered part
    float sm3 = 0.f;                  // sum(mask3D)
    float a2 = 0.f, b2 = 0.f;         // 2D part

    const int n_iter = N >> 2;        // 4 samples / iteration
    const int v4     = V >> 2;        // m3d float4 count
    const int m4n    = M >> 2;        // 2D float4 count

    const int4*   idx4 = reinterpret_cast<const int4*>(index);
    const int4*   mid4 = reinterpret_cast<const int4*>(midxyz);
    const float4* m34  = reinterpret_cast<const float4*>(m3d);
    const float4* o4   = reinterpret_cast<const float4*>(o2d);
    const float4* q4   = reinterpret_cast<const float4*>(m2d);

    // ======== main interleaved loop: streams + gathers together ========
    for (int i = tid; i < n_iter; i += stride) {
        // ---- stream: up to 4 coalesced m3d float4 (sub-streams k*n_iter+i) ----
        #pragma unroll
        for (int k = 0; k < 4; ++k) {
            const int j = k * n_iter + i;
            if (j < v4) {
                const float4 m = m34[j];               // default: stays in L2
                sm3 += (m.x + m.y) + (m.z + m.w);
            }
        }
        // ---- stream: one 2D float4 pair ----
        if (i < m4n) {
            const float4 o = o4[i];                    // o2d reused by gathers
            const float4 m = ldcs_float4(q4 + i);      // one-shot
            a2 += o.x * m.x + o.y * m.y + o.z * m.z + o.w * m.w;
            b2 += (o.x + m.x) + (o.y + m.y) + (o.z + m.z) + (o.w + m.w);
        }
        // ---- gather: 4 scattered samples ----
        const int4 id = ldcs_int4(idx4 + i);
        const int4 ma = ldcs_int4(mid4 + 3 * i + 0);
        const int4 mb = ldcs_int4(mid4 + 3 * i + 1);
        const int4 mc = ldcs_int4(mid4 + 3 * i + 2);
        process_sample(o2d, m3d, id.x, ma.x, ma.y, ma.z, D, inter2, sumv);
        process_sample(o2d, m3d, id.y, ma.w, mb.x, mb.y, D, inter2, sumv);
        process_sample(o2d, m3d, id.z, mb.z, mb.w, mc.x, D, inter2, sumv);
        process_sample(o2d, m3d, id.w, mc.y, mc.z, mc.w, D, inter2, sumv);
    }

    // ======== generic tails (no-ops for the benchmark shapes) ========
    for (int i = (n_iter << 2) + tid; i < N; i += stride) {
        process_sample(o2d, m3d, index[i],
                       midxyz[3 * i], midxyz[3 * i + 1], midxyz[3 * i + 2],
                       D, inter2, sumv);
    }
    for (int j = 4 * n_iter + tid; j < v4; j += stride) {
        const float4 m = m34[j];
        sm3 += (m.x + m.y) + (m.z + m.w);
    }
    for (int i = (v4 << 2) + tid; i < V; i += stride) sm3 += m3d[i];
    for (int i = n_iter + tid; i < m4n; i += stride) {
        const float4 o = o4[i];
        const float4 m = q4[i];
        a2 += o.x * m.x + o.y * m.y + o.z * m.z + o.w * m.w;
        b2 += (o.x + m.x) + (o.y + m.y) + (o.z + m.z) + (o.w + m.w);
    }
    for (int i = (m4n << 2) + tid; i < M; i += stride) {
        const float o = o2d[i], m = m2d[i];
        a2 += o * m;
        b2 += o + m;
    }

    block_reduce_pair(a2, b2, &g_acc[0], &g_acc[1]);
    block_reduce_pair(inter2, sumv, &g_acc[2], &g_acc[3]);
    block_reduce_pair(sm3, 0.f, &g_acc[4], &g_acc[4]);

    // ======== fused finalize: last block computes the loss ========
    __syncthreads();
    if (threadIdx.x == 0) {
        __threadfence();
        const unsigned t = atomicAdd(&g_done, 1u);
        if (t == gridDim.x - 1u) {
            const double eps = 1e-8;
            const double A1 = g_acc[0], B1 = g_acc[1];
            const double I2 = g_acc[2], SV = g_acc[3], SM = g_acc[4];
            const double l1 = 1.0 - (A1 + eps) / ((B1 - A1) + eps);
            const double l2 = 1.0 - (I2 + eps) / ((SV + SM - I2) + eps);
            out[0] = (float)l1;
            out[1] = (float)l2;
            out[2] = (float)(l1 + l2);
        }
    }
}

// ---------------------------------------------------------------------------
extern "C" void kernel_launch(void* const* d_in, const int* in_sizes, int n_in,
                              void* d_out, int out_size) {
    const float* o2d    = (const float*)d_in[0];
    const float* m2d    = (const float*)d_in[1];
    const float* m3d    = (const float*)d_in[2];
    const int*   index  = (const int*)  d_in[3];
    const int*   midxyz = (const int*)  d_in[4];

    const int M = in_sizes[0];        // H2*W2
    const int V = in_sizes[2];        // D^3
    const int N = in_sizes[3];        // samples

    int D = 1;
    while ((long long)(D + 1) * (D + 1) * (D + 1) <= (long long)V) ++D;
    if (D > DMAX) D = DMAX;

    float* out = (float*)d_out;

    const int TPB  = 256;
    const int GRID = 148 * 16;        // 2368 blocks

    zero_kernel<<<148 * 8, TPB>>>();
    fused_kernel<<<GRID, TPB>>>(o2d, m2d, m3d, index, midxyz, N, M, V, D, out);
}